// round 1
// baseline (speedup 1.0000x reference)
#include <cuda_runtime.h>
#include <cstdint>

// ---------------------------------------------------------------------------
// TTConv collapsed to a single 256->256 3x3 conv (+ per-channel bias).
//
//   out[b,oc,h,w] = sum_{ic,tap} W_eff[oc,ic,tap] * Xpad[b,ic,h+dh,w+dw] + bias_eff[oc]
//
//   W_eff[oc][ic][tap] = sum_r A[oc][ic][r] * conv_w[r][tap]
//   A[oc][ic][r]       = sum_{u,v} G1[a,u,r,i] G2[c,v,u,j] G3[d,0,v,k]
//   bias_eff[oc]       = sum_{ic,r} A[oc][ic][r] * conv_b[r]
//
// with oc = a*64 + c*8 + d (O=(4,8,8)), ic = i*64 + j*8 + k (M=(4,8,8)).
// ---------------------------------------------------------------------------

#define BATCH   8
#define CH      256
#define HH      64
#define WW      64
#define KTOT    (CH * 9)        // 2304
#define MTOT    (BATCH * HH * WW) // 32768

// Scratch (allocation-free: __device__ globals)
__device__ float g_T[4 * 16 * 4 * 8 * 16 * 8];   // [a][r][i][c][v][j]  (262144)
__device__ float g_A[CH * 16 * CH];              // [ic][r][oc]          (1048576)
__device__ float g_W[KTOT * CH];                 // [k=ic*9+tap][oc]     (589824)
__device__ float g_bias[CH];

// ---------------- Stage A: T[a,r,i,c,v,j] = sum_u G1[a,u,r,i] G2[c,v,u,j] ---
__global__ void stageA(const float* __restrict__ core1, const float* __restrict__ core2) {
    int idx = blockIdx.x * blockDim.x + threadIdx.x;   // < 262144
    int j = idx & 7;
    int v = (idx >> 3) & 15;
    int c = (idx >> 7) & 7;
    int i = (idx >> 10) & 3;
    int r = (idx >> 12) & 15;
    int a = (idx >> 16) & 3;
    float s = 0.f;
#pragma unroll
    for (int u = 0; u < 16; u++)
        s += core1[(a * 16 + u) * 64 + r * 4 + i] * core2[(c * 16 + v) * 128 + u * 8 + j];
    g_T[idx] = s;
}

// ---------------- Stage B: A[ic][r][oc] = sum_v T[a,r,i,c,v,j] * G3[d,v,k] --
__global__ void stageB(const float* __restrict__ core3) {
    int idx = blockIdx.x * blockDim.x + threadIdx.x;   // < 1048576
    int oc = idx & 255;
    int r  = (idx >> 8) & 15;
    int ic = idx >> 12;
    int k = ic & 7, j = (ic >> 3) & 7, i = ic >> 6;
    int d = oc & 7, c = (oc >> 3) & 7, a = oc >> 6;
    float s = 0.f;
#pragma unroll
    for (int v = 0; v < 16; v++)
        s += g_T[((((a * 16 + r) * 4 + i) * 8 + c) * 16 + v) * 8 + j] *
             core3[d * 128 + v * 8 + k];
    g_A[idx] = s;
}

// ---------------- Stage C: W[k][oc] = sum_r A[ic][r][oc] * conv_w[r][tap] ---
__global__ void stageC(const float* __restrict__ conv_w) {
    int idx = blockIdx.x * blockDim.x + threadIdx.x;   // < 589824
    int oc = idx & 255;
    int kk = idx >> 8;          // 0..2303
    int ic = kk / 9;
    int tap = kk - ic * 9;
    float s = 0.f;
#pragma unroll
    for (int r = 0; r < 16; r++)
        s += g_A[(ic * 16 + r) * 256 + oc] * conv_w[r * 9 + tap];
    g_W[idx] = s;
}

// ---------------- bias_eff[oc] = sum_{ic,r} A[ic][r][oc] * conv_b[r] --------
__global__ void biasK(const float* __restrict__ conv_b) {
    int oc = threadIdx.x;
    float s = 0.f;
    for (int ic = 0; ic < 256; ic++)
#pragma unroll
        for (int r = 0; r < 16; r++)
            s += g_A[(ic * 16 + r) * 256 + oc] * conv_b[r];
    g_bias[oc] = s;
}

// ---------------------------------------------------------------------------
// Main implicit-GEMM conv: C[oc][m] = sum_k W[k][oc] * Xim2col[k][m]
//   M = 32768 (m = b*4096 + h*64 + w), N = 256 (oc), K = 2304 (ic*9 + tap)
// Block tile 128(oc) x 128(m) x 8(k), 256 threads, 8x8 per thread (4+4 split).
// ---------------------------------------------------------------------------
#define BM 128
#define BN 128
#define BK 8
#define NKT (KTOT / BK)   // 288

__global__ __launch_bounds__(256, 2)
void conv_gemm(const float* __restrict__ X, float* __restrict__ out) {
    __shared__ float Ws[2][BK][BN];   // weights: [k][oc]
    __shared__ float Xs[2][BK][BM];   // input patches: [k][m]

    const int tid = threadIdx.x;
    const int m0  = blockIdx.x * BM;
    const int oc0 = blockIdx.y * BN;

    // loader mapping: each thread loads k-row (tid>>5), 4 m-cols (lcol + e*32)
    const int lrow = tid >> 5;
    const int lcol = tid & 31;

    int mb[4], mh[4], mw[4];
#pragma unroll
    for (int e = 0; e < 4; e++) {
        int m = m0 + lcol + e * 32;
        mb[e] = m >> 12;
        mh[e] = (m >> 6) & 63;
        mw[e] = m & 63;
    }

    float acc[8][8];
#pragma unroll
    for (int i = 0; i < 8; i++)
#pragma unroll
        for (int j = 0; j < 8; j++) acc[i][j] = 0.f;

    auto load_tiles = [&](int kt, int buf) {
        int kg = kt * BK + lrow;
        int ic = kg / 9;
        int t  = kg - ic * 9;
        int dh = t / 3 - 1;
        int dw = t - (t / 3) * 3 - 1;
        const float* Xp = X + ic * (HH * WW);
#pragma unroll
        for (int e = 0; e < 4; e++) {
            int hs = mh[e] + dh, ws = mw[e] + dw;
            float v = 0.f;
            if (((unsigned)hs < 64u) & ((unsigned)ws < 64u))
                v = Xp[mb[e] * (CH * HH * WW) + hs * 64 + ws];
            Xs[buf][lrow][lcol + e * 32] = v;
        }
        const float4* Wp = (const float4*)(g_W + kg * 256 + oc0);
        ((float4*)Ws[buf][lrow])[lcol] = Wp[lcol];
    };

    load_tiles(0, 0);
    __syncthreads();

    const int tx = tid & 15;   // m-fragment selector
    const int ty = tid >> 4;   // oc-fragment selector

    for (int kt = 0; kt < NKT; kt++) {
        const int cbuf = kt & 1;
        if (kt + 1 < NKT) load_tiles(kt + 1, cbuf ^ 1);
#pragma unroll
        for (int k = 0; k < BK; k++) {
            float af[8], bf[8];
            *(float4*)&af[0] = *(const float4*)&Ws[cbuf][k][ty * 4];
            *(float4*)&af[4] = *(const float4*)&Ws[cbuf][k][64 + ty * 4];
            *(float4*)&bf[0] = *(const float4*)&Xs[cbuf][k][tx * 4];
            *(float4*)&bf[4] = *(const float4*)&Xs[cbuf][k][64 + tx * 4];
#pragma unroll
            for (int i = 0; i < 8; i++)
#pragma unroll
                for (int j = 0; j < 8; j++)
                    acc[i][j] += af[i] * bf[j];
        }
        __syncthreads();
    }

    // Epilogue: rows = oc {oc0 + ih*64 + ty*4 + i}, cols = m {m0 + jh*64 + tx*4 + j}
#pragma unroll
    for (int ih = 0; ih < 2; ih++) {
#pragma unroll
        for (int i = 0; i < 4; i++) {
            int oc = oc0 + ih * 64 + ty * 4 + i;
            float bv = g_bias[oc];
            int ai = ih * 4 + i;
#pragma unroll
            for (int jh = 0; jh < 2; jh++) {
                int m = m0 + jh * 64 + tx * 4;
                int b = m >> 12;
                int hw = m & 4095;
                float* po = out + b * (CH * HH * WW) + oc * (HH * WW) + hw;
                float4 v = make_float4(acc[ai][jh * 4 + 0] + bv,
                                       acc[ai][jh * 4 + 1] + bv,
                                       acc[ai][jh * 4 + 2] + bv,
                                       acc[ai][jh * 4 + 3] + bv);
                *(float4*)po = v;
            }
        }
    }
}

// ---------------------------------------------------------------------------
extern "C" void kernel_launch(void* const* d_in, const int* in_sizes, int n_in,
                              void* d_out, int out_size) {
    const float* X      = (const float*)d_in[0];
    const float* conv_w = (const float*)d_in[1];
    const float* conv_b = (const float*)d_in[2];
    const float* core1  = (const float*)d_in[3];
    const float* core2  = (const float*)d_in[4];
    const float* core3  = (const float*)d_in[5];
    float* out = (float*)d_out;

    stageA<<<262144 / 256, 256>>>(core1, core2);
    stageB<<<1048576 / 256, 256>>>(core3);
    stageC<<<589824 / 256, 256>>>(conv_w);
    biasK<<<1, 256>>>(conv_b);

    dim3 grid(MTOT / BM, CH / BN);   // (256, 2)
    conv_gemm<<<grid, 256>>>(X, out);
}

// round 2
// speedup vs baseline: 1.1262x; 1.1262x over previous
#include <cuda_runtime.h>
#include <cstdint>

// ---------------------------------------------------------------------------
// TTConv collapsed to a single 256->256 3x3 conv (+ per-channel bias).
//
//   out[b,oc,h,w] = sum_{ic,tap} W_eff[oc,ic,tap] * Xpad[b,ic,h+dh,w+dw] + bias_eff[oc]
//
//   W_eff[oc][ic][tap] = sum_r A[oc][ic][r] * conv_w[r][tap]
//   A[oc][ic][r]       = sum_{u,v} G1[a,u,r,i] G2[c,v,u,j] G3[d,0,v,k]
//   bias_eff[oc]       = sum_{ic,r} A[oc][ic][r] * conv_b[r]
//
// with oc = a*64 + c*8 + d (O=(4,8,8)), ic = i*64 + j*8 + k (M=(4,8,8)).
// ---------------------------------------------------------------------------

#define BATCH   8
#define CH      256
#define HH      64
#define WW      64
#define KTOT    (CH * 9)        // 2304
#define MTOT    (BATCH * HH * WW) // 32768

// Scratch (allocation-free: __device__ globals)
__device__ float g_T[4 * 16 * 4 * 8 * 16 * 8];   // [a][r][i][c][v][j]  (262144)
__device__ float g_A[CH * 16 * CH];              // [ic][r][oc]          (1048576)
__device__ float g_W[KTOT * CH];                 // [k=ic*9+tap][oc]     (589824)
__device__ float g_bias[CH];

// ---------------- Stage A: T[a,r,i,c,v,j] = sum_u G1[a,u,r,i] G2[c,v,u,j] ---
__global__ void stageA(const float* __restrict__ core1, const float* __restrict__ core2) {
    int idx = blockIdx.x * blockDim.x + threadIdx.x;   // < 262144
    int j = idx & 7;
    int v = (idx >> 3) & 15;
    int c = (idx >> 7) & 7;
    int i = (idx >> 10) & 3;
    int r = (idx >> 12) & 15;
    int a = (idx >> 16) & 3;
    float s = 0.f;
#pragma unroll
    for (int u = 0; u < 16; u++)
        s += core1[(a * 16 + u) * 64 + r * 4 + i] * core2[(c * 16 + v) * 128 + u * 8 + j];
    g_T[idx] = s;
}

// ---------------- Stage B: A[ic][r][oc] = sum_v T[a,r,i,c,v,j] * G3[d,v,k] --
__global__ void stageB(const float* __restrict__ core3) {
    int idx = blockIdx.x * blockDim.x + threadIdx.x;   // < 1048576
    int oc = idx & 255;
    int r  = (idx >> 8) & 15;
    int ic = idx >> 12;
    int k = ic & 7, j = (ic >> 3) & 7, i = ic >> 6;
    int d = oc & 7, c = (oc >> 3) & 7, a = oc >> 6;
    float s = 0.f;
#pragma unroll
    for (int v = 0; v < 16; v++)
        s += g_T[((((a * 16 + r) * 4 + i) * 8 + c) * 16 + v) * 8 + j] *
             core3[d * 128 + v * 8 + k];
    g_A[idx] = s;
}

// ---------------- Stage C: W[k][oc] = sum_r A[ic][r][oc] * conv_w[r][tap] ---
__global__ void stageC(const float* __restrict__ conv_w) {
    int idx = blockIdx.x * blockDim.x + threadIdx.x;   // < 589824
    int oc = idx & 255;
    int kk = idx >> 8;          // 0..2303
    int ic = kk / 9;
    int tap = kk - ic * 9;
    float s = 0.f;
#pragma unroll
    for (int r = 0; r < 16; r++)
        s += g_A[(ic * 16 + r) * 256 + oc] * conv_w[r * 9 + tap];
    g_W[idx] = s;
}

// ---------------- bias_eff[oc] = sum_{ic,r} A[ic][r][oc] * conv_b[r] --------
// One block per oc; 256 threads stride over ic; shared tree reduce.
__global__ void biasK(const float* __restrict__ conv_b) {
    __shared__ float red[256];
    const int oc = blockIdx.x;
    const int t  = threadIdx.x;
    // thread t handles ic = t (exactly 256 ics, 256 threads)
    float s = 0.f;
#pragma unroll
    for (int r = 0; r < 16; r++)
        s += g_A[(t * 16 + r) * 256 + oc] * conv_b[r];
    red[t] = s;
    __syncthreads();
#pragma unroll
    for (int off = 128; off > 0; off >>= 1) {
        if (t < off) red[t] += red[t + off];
        __syncthreads();
    }
    if (t == 0) g_bias[oc] = red[0];
}

// ---------------------------------------------------------------------------
// Main implicit-GEMM conv: C[oc][m] = sum_k W[k][oc] * Xim2col[k][m]
//   M = 32768 (m = b*4096 + h*64 + w), N = 256 (oc), K = 2304 (ic*9 + tap)
// Block tile 128(oc) x 128(m) x 8(k), 256 threads, 8x8 per thread (4+4 split).
// ---------------------------------------------------------------------------
#define BM 128
#define BN 128
#define BK 8
#define NKT (KTOT / BK)   // 288

__global__ __launch_bounds__(256, 2)
void conv_gemm(const float* __restrict__ X, float* __restrict__ out) {
    __shared__ float Ws[2][BK][BN];   // weights: [k][oc]
    __shared__ float Xs[2][BK][BM];   // input patches: [k][m]

    const int tid = threadIdx.x;
    const int m0  = blockIdx.x * BM;
    const int oc0 = blockIdx.y * BN;

    // loader mapping: each thread loads k-row (tid>>5), 4 m-cols (lcol + e*32)
    const int lrow = tid >> 5;
    const int lcol = tid & 31;

    int mb[4], mh[4], mw[4];
#pragma unroll
    for (int e = 0; e < 4; e++) {
        int m = m0 + lcol + e * 32;
        mb[e] = m >> 12;
        mh[e] = (m >> 6) & 63;
        mw[e] = m & 63;
    }

    float acc[8][8];
#pragma unroll
    for (int i = 0; i < 8; i++)
#pragma unroll
        for (int j = 0; j < 8; j++) acc[i][j] = 0.f;

    auto load_tiles = [&](int kt, int buf) {
        int kg = kt * BK + lrow;
        int ic = kg / 9;
        int t  = kg - ic * 9;
        int dh = t / 3 - 1;
        int dw = t - (t / 3) * 3 - 1;
        const float* Xp = X + ic * (HH * WW);
#pragma unroll
        for (int e = 0; e < 4; e++) {
            int hs = mh[e] + dh, ws = mw[e] + dw;
            float v = 0.f;
            if (((unsigned)hs < 64u) & ((unsigned)ws < 64u))
                v = Xp[mb[e] * (CH * HH * WW) + hs * 64 + ws];
            Xs[buf][lrow][lcol + e * 32] = v;
        }
        const float4* Wp = (const float4*)(g_W + kg * 256 + oc0);
        ((float4*)Ws[buf][lrow])[lcol] = Wp[lcol];
    };

    load_tiles(0, 0);
    __syncthreads();

    const int tx = tid & 15;   // m-fragment selector
    const int ty = tid >> 4;   // oc-fragment selector

    for (int kt = 0; kt < NKT; kt++) {
        const int cbuf = kt & 1;
        if (kt + 1 < NKT) load_tiles(kt + 1, cbuf ^ 1);
#pragma unroll
        for (int k = 0; k < BK; k++) {
            float af[8], bf[8];
            *(float4*)&af[0] = *(const float4*)&Ws[cbuf][k][ty * 4];
            *(float4*)&af[4] = *(const float4*)&Ws[cbuf][k][64 + ty * 4];
            *(float4*)&bf[0] = *(const float4*)&Xs[cbuf][k][tx * 4];
            *(float4*)&bf[4] = *(const float4*)&Xs[cbuf][k][64 + tx * 4];
#pragma unroll
            for (int i = 0; i < 8; i++)
#pragma unroll
                for (int j = 0; j < 8; j++)
                    acc[i][j] += af[i] * bf[j];
        }
        __syncthreads();
    }

    // Epilogue: rows = oc {oc0 + ih*64 + ty*4 + i}, cols = m {m0 + jh*64 + tx*4 + j}
#pragma unroll
    for (int ih = 0; ih < 2; ih++) {
#pragma unroll
        for (int i = 0; i < 4; i++) {
            int oc = oc0 + ih * 64 + ty * 4 + i;
            float bv = g_bias[oc];
            int ai = ih * 4 + i;
#pragma unroll
            for (int jh = 0; jh < 2; jh++) {
                int m = m0 + jh * 64 + tx * 4;
                int b = m >> 12;
                int hw = m & 4095;
                float* po = out + b * (CH * HH * WW) + oc * (HH * WW) + hw;
                float4 v = make_float4(acc[ai][jh * 4 + 0] + bv,
                                       acc[ai][jh * 4 + 1] + bv,
                                       acc[ai][jh * 4 + 2] + bv,
                                       acc[ai][jh * 4 + 3] + bv);
                *(float4*)po = v;
            }
        }
    }
}

// ---------------------------------------------------------------------------
extern "C" void kernel_launch(void* const* d_in, const int* in_sizes, int n_in,
                              void* d_out, int out_size) {
    const float* X      = (const float*)d_in[0];
    const float* conv_w = (const float*)d_in[1];
    const float* conv_b = (const float*)d_in[2];
    const float* core1  = (const float*)d_in[3];
    const float* core2  = (const float*)d_in[4];
    const float* core3  = (const float*)d_in[5];
    float* out = (float*)d_out;

    stageA<<<262144 / 256, 256>>>(core1, core2);
    stageB<<<1048576 / 256, 256>>>(core3);
    stageC<<<589824 / 256, 256>>>(conv_w);
    biasK<<<CH, 256>>>(conv_b);

    dim3 grid(MTOT / BM, CH / BN);   // (256, 2)
    conv_gemm<<<grid, 256>>>(X, out);
}

// round 7
// speedup vs baseline: 2.2167x; 1.9684x over previous
#include <cuda_runtime.h>
#include <cuda_bf16.h>
#include <cstdint>

// ===========================================================================
// TTConv collapsed to a 256->256 3x3 conv (+ bias).
// Main GEMM on mma.sync bf16 (hi/lo 3-term split) — sm_103-baseline ISA only
// (the harness targets sm_103, not sm_103a: no tcgen05 allowed).
// ===========================================================================

#define BATCH 8
#define CH    256
#define HH    64
#define WW    64
#define HWIMG (HH*WW)

// ---------------- scratch (__device__ globals; no allocation) --------------
__device__ float g_T[4 * 16 * 4 * 8 * 16 * 8];
__device__ float g_A[CH * 16 * CH];          // [ic][r][oc]
__device__ float g_W[2304 * CH];             // [ic*9+tap][oc]
__device__ float g_bias[CH];
__device__ alignas(256) __nv_bfloat16 g_W2hi[9 * CH * CH];      // [tap][oc][ic]
__device__ alignas(256) __nv_bfloat16 g_W2lo[9 * CH * CH];
__device__ alignas(256) __nv_bfloat16 g_Xhi[BATCH * HWIMG * CH]; // [b][h][w][ic]
__device__ alignas(256) __nv_bfloat16 g_Xlo[BATCH * HWIMG * CH];

// ---------------- PTX helpers (all sm_80+ baseline) -------------------------
__device__ __forceinline__ uint32_t smem_u32(const void* p) {
    uint32_t a;
    asm("{ .reg .u64 t; cvta.to.shared.u64 t, %1; cvt.u32.u64 %0, t; }" : "=r"(a) : "l"(p));
    return a;
}
__device__ __forceinline__ void cp16(uint32_t d, const void* s, int sz) {
    asm volatile("cp.async.cg.shared.global [%0], [%1], 16, %2;" :: "r"(d), "l"(s), "r"(sz) : "memory");
}
#define CP_COMMIT() asm volatile("cp.async.commit_group;" ::: "memory")
#define CP_WAIT(n)  asm volatile("cp.async.wait_group %0;" :: "n"(n) : "memory")

__device__ __forceinline__ void ldsm4(uint32_t* r, uint32_t addr) {
    asm volatile("ldmatrix.sync.aligned.m8n8.x4.shared.b16 {%0,%1,%2,%3}, [%4];"
        : "=r"(r[0]), "=r"(r[1]), "=r"(r[2]), "=r"(r[3]) : "r"(addr));
}
__device__ __forceinline__ void mma16816(float* c, const uint32_t* a, const uint32_t* b) {
    asm volatile(
        "mma.sync.aligned.m16n8k16.row.col.f32.bf16.bf16.f32 "
        "{%0,%1,%2,%3}, {%4,%5,%6,%7}, {%8,%9}, {%0,%1,%2,%3};"
        : "+f"(c[0]), "+f"(c[1]), "+f"(c[2]), "+f"(c[3])
        : "r"(a[0]), "r"(a[1]), "r"(a[2]), "r"(a[3]), "r"(b[0]), "r"(b[1]));
}

// ---------------- Stage A/B/C + bias (weight folding) ----------------------
__global__ void stageA(const float* __restrict__ core1, const float* __restrict__ core2) {
    int idx = blockIdx.x * blockDim.x + threadIdx.x;
    int j = idx & 7, v = (idx >> 3) & 15, c = (idx >> 7) & 7;
    int i = (idx >> 10) & 3, r = (idx >> 12) & 15, a = (idx >> 16) & 3;
    float s = 0.f;
#pragma unroll
    for (int u = 0; u < 16; u++)
        s += core1[(a * 16 + u) * 64 + r * 4 + i] * core2[(c * 16 + v) * 128 + u * 8 + j];
    g_T[idx] = s;
}
__global__ void stageB(const float* __restrict__ core3) {
    int idx = blockIdx.x * blockDim.x + threadIdx.x;
    int oc = idx & 255, r = (idx >> 8) & 15, ic = idx >> 12;
    int k = ic & 7, j = (ic >> 3) & 7, i = ic >> 6;
    int d = oc & 7, c = (oc >> 3) & 7, a = oc >> 6;
    float s = 0.f;
#pragma unroll
    for (int v = 0; v < 16; v++)
        s += g_T[((((a * 16 + r) * 4 + i) * 8 + c) * 16 + v) * 8 + j] * core3[d * 128 + v * 8 + k];
    g_A[idx] = s;
}
__global__ void stageC(const float* __restrict__ conv_w) {
    int idx = blockIdx.x * blockDim.x + threadIdx.x;
    int oc = idx & 255, kk = idx >> 8;
    int ic = kk / 9, tap = kk - ic * 9;
    float s = 0.f;
#pragma unroll
    for (int r = 0; r < 16; r++)
        s += g_A[(ic * 16 + r) * 256 + oc] * conv_w[r * 9 + tap];
    g_W[idx] = s;
}
__global__ void biasK(const float* __restrict__ conv_b) {
    __shared__ float red[256];
    const int oc = blockIdx.x, t = threadIdx.x;
    float s = 0.f;
#pragma unroll
    for (int r = 0; r < 16; r++)
        s += g_A[(t * 16 + r) * 256 + oc] * conv_b[r];
    red[t] = s;
    __syncthreads();
#pragma unroll
    for (int off = 128; off > 0; off >>= 1) {
        if (t < off) red[t] += red[t + off];
        __syncthreads();
    }
    if (t == 0) g_bias[oc] = red[0];
}

// ---------------- weight reorder + hi/lo split: W2[tap][oc][ic] ------------
__global__ void splitW() {
    int idx = blockIdx.x * 256 + threadIdx.x;   // < 9*256*256
    int ic = idx & 255, oc = (idx >> 8) & 255, tap = idx >> 16;
    float w = g_W[(ic * 9 + tap) * 256 + oc];
    __nv_bfloat16 hi = __float2bfloat16(w);
    g_W2hi[idx] = hi;
    g_W2lo[idx] = __float2bfloat16(w - __bfloat162float(hi));
}

// ---------------- X transpose + hi/lo split: X_t[b][h][w][ic] --------------
__global__ void splitX(const float* __restrict__ X) {
    __shared__ float tile[32][33];
    const int b = blockIdx.z;
    const int hwt = blockIdx.x * 32, ict = blockIdx.y * 32;
    const int tx = threadIdx.x & 31, ty = threadIdx.x >> 5;   // ty 0..7
#pragma unroll
    for (int i = 0; i < 4; i++) {
        int ic = ict + ty + i * 8;
        tile[ty + i * 8][tx] = X[((b * CH + ic) * HWIMG) + hwt + tx];
    }
    __syncthreads();
#pragma unroll
    for (int i = 0; i < 4; i++) {
        int hw = hwt + ty + i * 8;
        int ic = ict + tx;
        float v = tile[tx][ty + i * 8];
        __nv_bfloat16 hi = __float2bfloat16(v);
        long o = (long)(b * HWIMG + hw) * CH + ic;
        g_Xhi[o] = hi;
        g_Xlo[o] = __float2bfloat16(v - __bfloat162float(hi));
    }
}

// ---------------------------------------------------------------------------
// Main mma.sync kernel: CTA tile 128(m) x 128(oc), K = 9 taps x 8 ic-chunks
// of 32 = 72 chunks. 4-stage cp.async pipeline. 8 warps (4x2), warp 32x64.
// bf16 3-term: Ah*Bh + Ah*Bl + Al*Bh, fp32 accumulate.
// Smem rows are 32 bf16 padded to 80 B pitch (16*5) -> ldmatrix conflict-free.
// ---------------------------------------------------------------------------
#define PITCH 80
#define OFF_AH 0
#define OFF_AL (128 * PITCH)
#define OFF_BH (2 * 128 * PITCH)
#define OFF_BL (3 * 128 * PITCH)
#define STG    (4 * 128 * PITCH)       // 40960 per stage
#define NSTAGE 4
#define SMEM_TOTAL (STG * NSTAGE)      // 163840
#define NC 72

__global__ __launch_bounds__(256, 1) void conv_mma(float* __restrict__ out) {
    extern __shared__ char smem[];
    const uint32_t sb = smem_u32(smem);
    const int tid = threadIdx.x;
    const int l = tid & 31, wid = tid >> 5;
    const int wm = wid & 3, wn = wid >> 2;       // warp tile origin (wm*32, wn*64)
    const int m0  = blockIdx.x * 128;
    const int oc0 = blockIdx.y * 128;
    const int b   = m0 >> 12;

    // loader indices: thread -> (row 0..127, 32B half)
    const int lrow = tid >> 1, lhalf = tid & 1;
    const int lm = m0 + lrow;
    const int lh = (lm >> 6) & 63, lw = lm & 63;

    auto load = [&](int c, int s) {
        const int tap = c >> 3;                  // c = tap*8 + ic-chunk
        const int icc = (c & 7) * 32;
        const int dh = tap / 3 - 1, dw = tap % 3 - 1;
        const uint32_t base = sb + s * STG;
        // A (hi & lo): 128 rows x 64 B, halo zero-fill
        int hv = lh + dh, wv = lw + dw;
        bool ok = ((unsigned)hv < 64u) & ((unsigned)wv < 64u);
        int sz = ok ? 16 : 0;
        long pix = (long)(b << 12) + (ok ? hv * 64 + wv : 0);
        const __nv_bfloat16* sah = g_Xhi + pix * CH + icc + lhalf * 16;
        const __nv_bfloat16* sal = g_Xlo + pix * CH + icc + lhalf * 16;
        uint32_t da = base + lrow * PITCH + lhalf * 32;
        cp16(da + OFF_AH,      sah,     sz);
        cp16(da + OFF_AH + 16, sah + 8, sz);
        cp16(da + OFF_AL,      sal,     sz);
        cp16(da + OFF_AL + 16, sal + 8, sz);
        // B (hi & lo): 128 oc rows x 64 B
        const __nv_bfloat16* sbh = g_W2hi + ((tap * 256 + oc0 + lrow) * 256 + icc + lhalf * 16);
        const __nv_bfloat16* sbl = g_W2lo + ((tap * 256 + oc0 + lrow) * 256 + icc + lhalf * 16);
        cp16(da + OFF_BH,      sbh,     16);
        cp16(da + OFF_BH + 16, sbh + 8, 16);
        cp16(da + OFF_BL,      sbl,     16);
        cp16(da + OFF_BL + 16, sbl + 8, 16);
        CP_COMMIT();
    };

    float acc[2][8][4];
#pragma unroll
    for (int i = 0; i < 2; i++)
#pragma unroll
        for (int j = 0; j < 8; j++)
#pragma unroll
            for (int q = 0; q < 4; q++) acc[i][j][q] = 0.f;

    load(0, 0); load(1, 1); load(2, 2);

    // fragment addressing (ldmatrix lane rows)
    const uint32_t a_row = wm * 32 + (l & 15);
    const uint32_t a_seg = (uint32_t)(l >> 4) * 16;
    const uint32_t b_row = wn * 64 + ((l >> 4) << 3) + (l & 7);
    const uint32_t b_seg = (uint32_t)((l >> 3) & 1) * 16;

    for (int c = 0; c < NC; ++c) {
        CP_WAIT(2);
        __syncthreads();
        const uint32_t base = sb + (uint32_t)(c & 3) * STG;
#pragma unroll
        for (int k16 = 0; k16 < 2; ++k16) {
            uint32_t ah[2][4], al[2][4], bh[4][4], bl[4][4];
#pragma unroll
            for (int mb = 0; mb < 2; ++mb) {
                uint32_t ad = base + (a_row + mb * 16) * PITCH + k16 * 32 + a_seg;
                ldsm4(ah[mb], ad + OFF_AH);
                ldsm4(al[mb], ad + OFF_AL);
            }
#pragma unroll
            for (int g = 0; g < 4; ++g) {
                uint32_t bd = base + (b_row + g * 16) * PITCH + k16 * 32 + b_seg;
                ldsm4(bh[g], bd + OFF_BH);
                ldsm4(bl[g], bd + OFF_BL);
            }
#pragma unroll
            for (int mb = 0; mb < 2; ++mb)
#pragma unroll
                for (int g = 0; g < 4; ++g)
#pragma unroll
                    for (int nb = 0; nb < 2; ++nb) {
                        float* cc = acc[mb][g * 2 + nb];
                        mma16816(cc, ah[mb], &bh[g][nb * 2]);
                        mma16816(cc, ah[mb], &bl[g][nb * 2]);
                        mma16816(cc, al[mb], &bh[g][nb * 2]);
                    }
        }
        if (c + 3 < NC) load(c + 3, (c + 3) & 3);
        else CP_COMMIT();                       // keep group accounting stable
    }

    // ---- epilogue: scatter accumulators + bias into out[b][oc][hw]
    const int hwbase = m0 & 4095;
    float* ob = out + (size_t)b * CH * HWIMG + hwbase;
#pragma unroll
    for (int mb = 0; mb < 2; ++mb) {
        int r0 = wm * 32 + mb * 16 + (l >> 2);
#pragma unroll
        for (int g = 0; g < 4; ++g)
#pragma unroll
            for (int nb = 0; nb < 2; ++nb) {
                int col = oc0 + wn * 64 + g * 16 + nb * 8 + (l & 3) * 2;
                float bv0 = g_bias[col], bv1 = g_bias[col + 1];
                float* v = acc[mb][g * 2 + nb];
                float* p0 = ob + (size_t)col * HWIMG;
                p0[r0]             = v[0] + bv0;
                p0[HWIMG + r0]     = v[1] + bv1;
                p0[r0 + 8]         = v[2] + bv0;
                p0[HWIMG + r0 + 8] = v[3] + bv1;
            }
    }
}

// ---------------------------------------------------------------------------
extern "C" void kernel_launch(void* const* d_in, const int* in_sizes, int n_in,
                              void* d_out, int out_size) {
    const float* X      = (const float*)d_in[0];
    const float* conv_w = (const float*)d_in[1];
    const float* conv_b = (const float*)d_in[2];
    const float* core1  = (const float*)d_in[3];
    const float* core2  = (const float*)d_in[4];
    const float* core3  = (const float*)d_in[5];
    float* out = (float*)d_out;

    stageA<<<1024, 256>>>(core1, core2);
    stageB<<<4096, 256>>>(core3);
    stageC<<<2304, 256>>>(conv_w);
    biasK<<<256, 256>>>(conv_b);
    splitW<<<2304, 256>>>();
    splitX<<<dim3(128, 8, 8), 256>>>(X);

    cudaFuncSetAttribute(conv_mma, cudaFuncAttributeMaxDynamicSharedMemorySize, SMEM_TOTAL);
    conv_mma<<<dim3(256, 2), 256, SMEM_TOTAL>>>(out);
}

// round 9
// speedup vs baseline: 3.0315x; 1.3676x over previous
#include <cuda_runtime.h>
#include <cuda_fp16.h>
#include <cstdint>

// ===========================================================================
// TTConv collapsed to a 256->256 3x3 conv (+ bias).
// Main GEMM on mma.sync fp16 (A single fp16, W hi/lo 2-term split).
// sm_103-baseline ISA only (no tcgen05 on this bench target).
// ===========================================================================

#define BATCH 8
#define CH    256
#define HH    64
#define WW    64
#define HWIMG (HH*WW)

// ---------------- scratch (__device__ globals; no allocation) --------------
__device__ float g_T[4 * 16 * 4 * 8 * 16 * 8];
__device__ float g_A[CH * 16 * CH];          // [ic][r][oc]
__device__ float g_W[2304 * CH];             // [ic*9+tap][oc]
__device__ float g_bias[CH];
__device__ alignas(256) __half g_W2hi[9 * CH * CH];      // [tap][oc][ic]
__device__ alignas(256) __half g_W2lo[9 * CH * CH];
__device__ alignas(256) __half g_Xh[BATCH * HWIMG * CH]; // [b][h][w][ic]

// ---------------- PTX helpers (all sm_80+ baseline) -------------------------
__device__ __forceinline__ uint32_t smem_u32(const void* p) {
    uint32_t a;
    asm("{ .reg .u64 t; cvta.to.shared.u64 t, %1; cvt.u32.u64 %0, t; }" : "=r"(a) : "l"(p));
    return a;
}
__device__ __forceinline__ void cp16(uint32_t d, const void* s, int sz) {
    asm volatile("cp.async.cg.shared.global [%0], [%1], 16, %2;" :: "r"(d), "l"(s), "r"(sz) : "memory");
}
#define CP_COMMIT() asm volatile("cp.async.commit_group;" ::: "memory")
#define CP_WAIT(n)  asm volatile("cp.async.wait_group %0;" :: "n"(n) : "memory")

__device__ __forceinline__ void ldsm4(uint32_t* r, uint32_t addr) {
    asm volatile("ldmatrix.sync.aligned.m8n8.x4.shared.b16 {%0,%1,%2,%3}, [%4];"
        : "=r"(r[0]), "=r"(r[1]), "=r"(r[2]), "=r"(r[3]) : "r"(addr));
}
__device__ __forceinline__ void mma16816(float* c, const uint32_t* a, const uint32_t* b) {
    asm volatile(
        "mma.sync.aligned.m16n8k16.row.col.f32.f16.f16.f32 "
        "{%0,%1,%2,%3}, {%4,%5,%6,%7}, {%8,%9}, {%0,%1,%2,%3};"
        : "+f"(c[0]), "+f"(c[1]), "+f"(c[2]), "+f"(c[3])
        : "r"(a[0]), "r"(a[1]), "r"(a[2]), "r"(a[3]), "r"(b[0]), "r"(b[1]));
}

// ---------------- Stage A/B/C + bias (weight folding) ----------------------
__global__ void stageA(const float* __restrict__ core1, const float* __restrict__ core2) {
    int idx = blockIdx.x * blockDim.x + threadIdx.x;
    int j = idx & 7, v = (idx >> 3) & 15, c = (idx >> 7) & 7;
    int i = (idx >> 10) & 3, r = (idx >> 12) & 15, a = (idx >> 16) & 3;
    float s = 0.f;
#pragma unroll
    for (int u = 0; u < 16; u++)
        s += core1[(a * 16 + u) * 64 + r * 4 + i] * core2[(c * 16 + v) * 128 + u * 8 + j];
    g_T[idx] = s;
}
__global__ void stageB(const float* __restrict__ core3) {
    int idx = blockIdx.x * blockDim.x + threadIdx.x;
    int oc = idx & 255, r = (idx >> 8) & 15, ic = idx >> 12;
    int k = ic & 7, j = (ic >> 3) & 7, i = ic >> 6;
    int d = oc & 7, c = (oc >> 3) & 7, a = oc >> 6;
    float s = 0.f;
#pragma unroll
    for (int v = 0; v < 16; v++)
        s += g_T[((((a * 16 + r) * 4 + i) * 8 + c) * 16 + v) * 8 + j] * core3[d * 128 + v * 8 + k];
    g_A[idx] = s;
}
__global__ void stageC(const float* __restrict__ conv_w) {
    int idx = blockIdx.x * blockDim.x + threadIdx.x;
    int oc = idx & 255, kk = idx >> 8;
    int ic = kk / 9, tap = kk - ic * 9;
    float s = 0.f;
#pragma unroll
    for (int r = 0; r < 16; r++)
        s += g_A[(ic * 16 + r) * 256 + oc] * conv_w[r * 9 + tap];
    g_W[idx] = s;
}
__global__ void biasK(const float* __restrict__ conv_b) {
    __shared__ float red[256];
    const int oc = blockIdx.x, t = threadIdx.x;
    float s = 0.f;
#pragma unroll
    for (int r = 0; r < 16; r++)
        s += g_A[(t * 16 + r) * 256 + oc] * conv_b[r];
    red[t] = s;
    __syncthreads();
#pragma unroll
    for (int off = 128; off > 0; off >>= 1) {
        if (t < off) red[t] += red[t + off];
        __syncthreads();
    }
    if (t == 0) g_bias[oc] = red[0];
}

// ---------------- weight reorder + fp16 hi/lo split: W2[tap][oc][ic] -------
__global__ void splitW() {
    int idx = blockIdx.x * 256 + threadIdx.x;   // < 9*256*256
    int ic = idx & 255, oc = (idx >> 8) & 255, tap = idx >> 16;
    float w = g_W[(ic * 9 + tap) * 256 + oc];
    __half hi = __float2half(w);
    g_W2hi[idx] = hi;
    g_W2lo[idx] = __float2half(w - __half2float(hi));
}

// ---------------- X transpose to fp16: X_t[b][h][w][ic] --------------------
__global__ void splitX(const float* __restrict__ X) {
    __shared__ float tile[32][33];
    const int b = blockIdx.z;
    const int hwt = blockIdx.x * 32, ict = blockIdx.y * 32;
    const int tx = threadIdx.x & 31, ty = threadIdx.x >> 5;   // ty 0..7
#pragma unroll
    for (int i = 0; i < 4; i++) {
        int ic = ict + ty + i * 8;
        tile[ty + i * 8][tx] = X[((b * CH + ic) * HWIMG) + hwt + tx];
    }
    __syncthreads();
#pragma unroll
    for (int i = 0; i < 4; i++) {
        int hw = hwt + ty + i * 8;
        int ic = ict + tx;
        long o = (long)(b * HWIMG + hw) * CH + ic;
        g_Xh[o] = __float2half(tile[tx][ty + i * 8]);
    }
}

// ---------------------------------------------------------------------------
// Main mma.sync kernel: CTA tile 128(m) x 128(oc), K = 9 taps x 8 ic-chunks
// of 32 = 72 chunks. 4-stage cp.async pipeline. 8 warps (4x2), warp 32x64.
// fp16 2-term: A*Bh + A*Bl, fp32 accumulate.
// Smem rows are 32 fp16 padded to 80 B pitch (16*5) -> ldmatrix conflict-free.
// ---------------------------------------------------------------------------
#define PITCH 80
#define OFF_A  0
#define OFF_BH (128 * PITCH)
#define OFF_BL (2 * 128 * PITCH)
#define STG    (3 * 128 * PITCH)       // 30720 per stage
#define NSTAGE 4
#define SMEM_TOTAL (STG * NSTAGE)      // 122880
#define NC 72

__global__ __launch_bounds__(256, 1) void conv_mma(float* __restrict__ out) {
    extern __shared__ char smem[];
    const uint32_t sb = smem_u32(smem);
    const int tid = threadIdx.x;
    const int l = tid & 31, wid = tid >> 5;
    const int wm = wid & 3, wn = wid >> 2;       // warp tile origin (wm*32, wn*64)
    const int m0  = blockIdx.x * 128;
    const int oc0 = blockIdx.y * 128;
    const int b   = m0 >> 12;

    // loader indices: thread -> (row 0..127, 32B half)
    const int lrow = tid >> 1, lhalf = tid & 1;
    const int lm = m0 + lrow;
    const int lh = (lm >> 6) & 63, lw = lm & 63;

    auto load = [&](int c, int s) {
        const int tap = c >> 3;                  // c = tap*8 + ic-chunk
        const int icc = (c & 7) * 32;
        const int dh = tap / 3 - 1, dw = tap % 3 - 1;
        const uint32_t base = sb + s * STG;
        // A: 128 rows x 64 B, halo zero-fill
        int hv = lh + dh, wv = lw + dw;
        bool ok = ((unsigned)hv < 64u) & ((unsigned)wv < 64u);
        int sz = ok ? 16 : 0;
        long pix = (long)(b << 12) + (ok ? hv * 64 + wv : 0);
        const __half* sa = g_Xh + pix * CH + icc + lhalf * 16;
        uint32_t da = base + lrow * PITCH + lhalf * 32;
        cp16(da + OFF_A,      sa,     sz);
        cp16(da + OFF_A + 16, sa + 8, sz);
        // B (hi & lo): 128 oc rows x 64 B
        const __half* sbh = g_W2hi + ((tap * 256 + oc0 + lrow) * 256 + icc + lhalf * 16);
        const __half* sbl = g_W2lo + ((tap * 256 + oc0 + lrow) * 256 + icc + lhalf * 16);
        cp16(da + OFF_BH,      sbh,     16);
        cp16(da + OFF_BH + 16, sbh + 8, 16);
        cp16(da + OFF_BL,      sbl,     16);
        cp16(da + OFF_BL + 16, sbl + 8, 16);
        CP_COMMIT();
    };

    float acc[2][8][4];
#pragma unroll
    for (int i = 0; i < 2; i++)
#pragma unroll
        for (int j = 0; j < 8; j++)
#pragma unroll
            for (int q = 0; q < 4; q++) acc[i][j][q] = 0.f;

    load(0, 0); load(1, 1); load(2, 2);

    // fragment addressing (ldmatrix lane rows)
    const uint32_t a_row = wm * 32 + (l & 15);
    const uint32_t a_seg = (uint32_t)(l >> 4) * 16;
    const uint32_t b_row = wn * 64 + ((l >> 4) << 3) + (l & 7);
    const uint32_t b_seg = (uint32_t)((l >> 3) & 1) * 16;

    for (int c = 0; c < NC; ++c) {
        CP_WAIT(2);
        __syncthreads();
        const uint32_t base = sb + (uint32_t)(c & 3) * STG;
#pragma unroll
        for (int k16 = 0; k16 < 2; ++k16) {
            uint32_t ah[2][4], bh[4][4], bl[4][4];
#pragma unroll
            for (int mb = 0; mb < 2; ++mb) {
                uint32_t ad = base + (a_row + mb * 16) * PITCH + k16 * 32 + a_seg;
                ldsm4(ah[mb], ad + OFF_A);
            }
#pragma unroll
            for (int g = 0; g < 4; ++g) {
                uint32_t bd = base + (b_row + g * 16) * PITCH + k16 * 32 + b_seg;
                ldsm4(bh[g], bd + OFF_BH);
                ldsm4(bl[g], bd + OFF_BL);
            }
#pragma unroll
            for (int mb = 0; mb < 2; ++mb)
#pragma unroll
                for (int g = 0; g < 4; ++g)
#pragma unroll
                    for (int nb = 0; nb < 2; ++nb) {
                        float* cc = acc[mb][g * 2 + nb];
                        mma16816(cc, ah[mb], &bh[g][nb * 2]);
                        mma16816(cc, ah[mb], &bl[g][nb * 2]);
                    }
        }
        if (c + 3 < NC) load(c + 3, (c + 3) & 3);
        else CP_COMMIT();                       // keep group accounting stable
    }

    // ---- epilogue: scatter accumulators + bias into out[b][oc][hw]
    const int hwbase = m0 & 4095;
    float* ob = out + (size_t)b * CH * HWIMG + hwbase;
#pragma unroll
    for (int mb = 0; mb < 2; ++mb) {
        int r0 = wm * 32 + mb * 16 + (l >> 2);
#pragma unroll
        for (int g = 0; g < 4; ++g)
#pragma unroll
            for (int nb = 0; nb < 2; ++nb) {
                int col = oc0 + wn * 64 + g * 16 + nb * 8 + (l & 3) * 2;
                float bv0 = g_bias[col], bv1 = g_bias[col + 1];
                float* v = acc[mb][g * 2 + nb];
                float* p0 = ob + (size_t)col * HWIMG;
                p0[r0]             = v[0] + bv0;
                p0[HWIMG + r0]     = v[1] + bv1;
                p0[r0 + 8]         = v[2] + bv0;
                p0[HWIMG + r0 + 8] = v[3] + bv1;
            }
    }
}

// ---------------------------------------------------------------------------
extern "C" void kernel_launch(void* const* d_in, const int* in_sizes, int n_in,
                              void* d_out, int out_size) {
    const float* X      = (const float*)d_in[0];
    const float* conv_w = (const float*)d_in[1];
    const float* conv_b = (const float*)d_in[2];
    const float* core1  = (const float*)d_in[3];
    const float* core2  = (const float*)d_in[4];
    const float* core3  = (const float*)d_in[5];
    float* out = (float*)d_out;

    stageA<<<1024, 256>>>(core1, core2);
    stageB<<<4096, 256>>>(core3);
    stageC<<<2304, 256>>>(conv_w);
    biasK<<<256, 256>>>(conv_b);
    splitW<<<2304, 256>>>();
    splitX<<<dim3(128, 8, 8), 256>>>(X);

    cudaFuncSetAttribute(conv_mma, cudaFuncAttributeMaxDynamicSharedMemorySize, SMEM_TOTAL);
    conv_mma<<<dim3(256, 2), 256, SMEM_TOTAL>>>(out);
}

// round 15
// speedup vs baseline: 4.2995x; 1.4183x over previous
#include <cuda_runtime.h>
#include <cuda_fp16.h>
#include <cstdint>

// ===========================================================================
// TTConv collapsed to a 256->256 3x3 conv (+ bias).
// Main GEMM on mma.sync fp16, single term (A fp16 x W fp16, fp32 accumulate).
// sm_103-baseline ISA only (no tcgen05 on this bench target).
// ===========================================================================

#define BATCH 8
#define CH    256
#define HH    64
#define WW    64
#define HWIMG (HH*WW)

// ---------------- scratch (__device__ globals; no allocation) --------------
__device__ float g_T[4 * 16 * 4 * 8 * 16 * 8];
__device__ float g_A[CH * 16 * CH];          // [ic][r][oc]
__device__ float g_W[2304 * CH];             // [ic*9+tap][oc]
__device__ float g_bias[CH];
__device__ alignas(256) __half g_W2[9 * CH * CH];        // [tap][oc][ic]
__device__ alignas(256) __half g_Xh[BATCH * HWIMG * CH]; // [b][h][w][ic]

// ---------------- PTX helpers (all sm_80+ baseline) -------------------------
__device__ __forceinline__ uint32_t smem_u32(const void* p) {
    uint32_t a;
    asm("{ .reg .u64 t; cvta.to.shared.u64 t, %1; cvt.u32.u64 %0, t; }" : "=r"(a) : "l"(p));
    return a;
}
__device__ __forceinline__ void cp16(uint32_t d, const void* s, int sz) {
    asm volatile("cp.async.cg.shared.global [%0], [%1], 16, %2;" :: "r"(d), "l"(s), "r"(sz) : "memory");
}
#define CP_COMMIT() asm volatile("cp.async.commit_group;" ::: "memory")
#define CP_WAIT(n)  asm volatile("cp.async.wait_group %0;" :: "n"(n) : "memory")

__device__ __forceinline__ void ldsm4(uint32_t* r, uint32_t addr) {
    asm volatile("ldmatrix.sync.aligned.m8n8.x4.shared.b16 {%0,%1,%2,%3}, [%4];"
        : "=r"(r[0]), "=r"(r[1]), "=r"(r[2]), "=r"(r[3]) : "r"(addr));
}
__device__ __forceinline__ void mma16816(float* c, const uint32_t* a, const uint32_t* b) {
    asm volatile(
        "mma.sync.aligned.m16n8k16.row.col.f32.f16.f16.f32 "
        "{%0,%1,%2,%3}, {%4,%5,%6,%7}, {%8,%9}, {%0,%1,%2,%3};"
        : "+f"(c[0]), "+f"(c[1]), "+f"(c[2]), "+f"(c[3])
        : "r"(a[0]), "r"(a[1]), "r"(a[2]), "r"(a[3]), "r"(b[0]), "r"(b[1]));
}

// ---------------- Stage A/B/C + bias (weight folding) ----------------------
__global__ void stageA(const float* __restrict__ core1, const float* __restrict__ core2) {
    int idx = blockIdx.x * blockDim.x + threadIdx.x;
    int j = idx & 7, v = (idx >> 3) & 15, c = (idx >> 7) & 7;
    int i = (idx >> 10) & 3, r = (idx >> 12) & 15, a = (idx >> 16) & 3;
    float s = 0.f;
#pragma unroll
    for (int u = 0; u < 16; u++)
        s += core1[(a * 16 + u) * 64 + r * 4 + i] * core2[(c * 16 + v) * 128 + u * 8 + j];
    g_T[idx] = s;
}
__global__ void stageB(const float* __restrict__ core3) {
    int idx = blockIdx.x * blockDim.x + threadIdx.x;
    int oc = idx & 255, r = (idx >> 8) & 15, ic = idx >> 12;
    int k = ic & 7, j = (ic >> 3) & 7, i = ic >> 6;
    int d = oc & 7, c = (oc >> 3) & 7, a = oc >> 6;
    float s = 0.f;
#pragma unroll
    for (int v = 0; v < 16; v++)
        s += g_T[((((a * 16 + r) * 4 + i) * 8 + c) * 16 + v) * 8 + j] * core3[d * 128 + v * 8 + k];
    g_A[idx] = s;
}
__global__ void stageC(const float* __restrict__ conv_w) {
    int idx = blockIdx.x * blockDim.x + threadIdx.x;
    int oc = idx & 255, kk = idx >> 8;
    int ic = kk / 9, tap = kk - ic * 9;
    float s = 0.f;
#pragma unroll
    for (int r = 0; r < 16; r++)
        s += g_A[(ic * 16 + r) * 256 + oc] * conv_w[r * 9 + tap];
    g_W[idx] = s;
}
__global__ void biasK(const float* __restrict__ conv_b) {
    __shared__ float red[256];
    const int oc = blockIdx.x, t = threadIdx.x;
    float s = 0.f;
#pragma unroll
    for (int r = 0; r < 16; r++)
        s += g_A[(t * 16 + r) * 256 + oc] * conv_b[r];
    red[t] = s;
    __syncthreads();
#pragma unroll
    for (int off = 128; off > 0; off >>= 1) {
        if (t < off) red[t] += red[t + off];
        __syncthreads();
    }
    if (t == 0) g_bias[oc] = red[0];
}

// ---------------- weight reorder to fp16: W2[tap][oc][ic] ------------------
__global__ void splitW() {
    int idx = blockIdx.x * 256 + threadIdx.x;   // < 9*256*256
    int ic = idx & 255, oc = (idx >> 8) & 255, tap = idx >> 16;
    g_W2[idx] = __float2half(g_W[(ic * 9 + tap) * 256 + oc]);
}

// ---------------- X transpose to fp16: X_t[b][h][w][ic] --------------------
__global__ void splitX(const float* __restrict__ X) {
    __shared__ float tile[32][33];
    const int b = blockIdx.z;
    const int hwt = blockIdx.x * 32, ict = blockIdx.y * 32;
    const int tx = threadIdx.x & 31, ty = threadIdx.x >> 5;   // ty 0..7
#pragma unroll
    for (int i = 0; i < 4; i++) {
        int ic = ict + ty + i * 8;
        tile[ty + i * 8][tx] = X[((b * CH + ic) * HWIMG) + hwt + tx];
    }
    __syncthreads();
#pragma unroll
    for (int i = 0; i < 4; i++) {
        int hw = hwt + ty + i * 8;
        int ic = ict + tx;
        long o = (long)(b * HWIMG + hw) * CH + ic;
        g_Xh[o] = __float2half(tile[tx][ty + i * 8]);
    }
}

// ---------------------------------------------------------------------------
// Main mma.sync kernel: CTA tile 128(m) x 128(oc), K = 9 taps x 8 ic-chunks
// of 32 = 72 chunks. 4-stage cp.async pipeline. 8 warps (4x2), warp 32x64.
// fp16 single-term, fp32 accumulate.
// Smem rows are 32 fp16 padded to 80 B pitch (16*5) -> ldmatrix conflict-free.
// ---------------------------------------------------------------------------
#define PITCH 80
#define OFF_A  0
#define OFF_B  (128 * PITCH)
#define STG    (2 * 128 * PITCH)       // 20480 per stage
#define NSTAGE 4
#define SMEM_TOTAL (STG * NSTAGE)      // 81920
#define NC 72

__global__ __launch_bounds__(256, 1) void conv_mma(float* __restrict__ out) {
    extern __shared__ char smem[];
    const uint32_t sb = smem_u32(smem);
    const int tid = threadIdx.x;
    const int l = tid & 31, wid = tid >> 5;
    const int wm = wid & 3, wn = wid >> 2;       // warp tile origin (wm*32, wn*64)
    const int m0  = blockIdx.x * 128;
    const int oc0 = blockIdx.y * 128;
    const int b   = m0 >> 12;

    // loader indices: thread -> (row 0..127, 32B half)
    const int lrow = tid >> 1, lhalf = tid & 1;
    const int lm = m0 + lrow;
    const int lh = (lm >> 6) & 63, lw = lm & 63;

    auto load = [&](int c, int s) {
        const int tap = c >> 3;                  // c = tap*8 + ic-chunk
        const int icc = (c & 7) * 32;
        const int dh = tap / 3 - 1, dw = tap % 3 - 1;
        const uint32_t base = sb + s * STG;
        // A: 128 rows x 64 B, halo zero-fill
        int hv = lh + dh, wv = lw + dw;
        bool ok = ((unsigned)hv < 64u) & ((unsigned)wv < 64u);
        int sz = ok ? 16 : 0;
        long pix = (long)(b << 12) + (ok ? hv * 64 + wv : 0);
        const __half* sa = g_Xh + pix * CH + icc + lhalf * 16;
        uint32_t da = base + lrow * PITCH + lhalf * 32;
        cp16(da + OFF_A,      sa,     sz);
        cp16(da + OFF_A + 16, sa + 8, sz);
        // B: 128 oc rows x 64 B
        const __half* sbw = g_W2 + ((tap * 256 + oc0 + lrow) * 256 + icc + lhalf * 16);
        cp16(da + OFF_B,      sbw,     16);
        cp16(da + OFF_B + 16, sbw + 8, 16);
        CP_COMMIT();
    };

    float acc[2][8][4];
#pragma unroll
    for (int i = 0; i < 2; i++)
#pragma unroll
        for (int j = 0; j < 8; j++)
#pragma unroll
            for (int q = 0; q < 4; q++) acc[i][j][q] = 0.f;

    load(0, 0); load(1, 1); load(2, 2);

    // fragment addressing (ldmatrix lane rows)
    const uint32_t a_row = wm * 32 + (l & 15);
    const uint32_t a_seg = (uint32_t)(l >> 4) * 16;
    const uint32_t b_row = wn * 64 + ((l >> 4) << 3) + (l & 7);
    const uint32_t b_seg = (uint32_t)((l >> 3) & 1) * 16;

    for (int c = 0; c < NC; ++c) {
        CP_WAIT(2);
        __syncthreads();
        const uint32_t base = sb + (uint32_t)(c & 3) * STG;
#pragma unroll
        for (int k16 = 0; k16 < 2; ++k16) {
            uint32_t ah[2][4], bh[4][4];
#pragma unroll
            for (int mb = 0; mb < 2; ++mb) {
                uint32_t ad = base + (a_row + mb * 16) * PITCH + k16 * 32 + a_seg;
                ldsm4(ah[mb], ad + OFF_A);
            }
#pragma unroll
            for (int g = 0; g < 4; ++g) {
                uint32_t bd = base + (b_row + g * 16) * PITCH + k16 * 32 + b_seg;
                ldsm4(bh[g], bd + OFF_B);
            }
#pragma unroll
            for (int mb = 0; mb < 2; ++mb)
#pragma unroll
                for (int g = 0; g < 4; ++g)
#pragma unroll
                    for (int nb = 0; nb < 2; ++nb)
                        mma16816(acc[mb][g * 2 + nb], ah[mb], &bh[g][nb * 2]);
        }
        if (c + 3 < NC) load(c + 3, (c + 3) & 3);
        else CP_COMMIT();                       // keep group accounting stable
    }

    // ---- epilogue: scatter accumulators + bias into out[b][oc][hw]
    const int hwbase = m0 & 4095;
    float* ob = out + (size_t)b * CH * HWIMG + hwbase;
#pragma unroll
    for (int mb = 0; mb < 2; ++mb) {
        int r0 = wm * 32 + mb * 16 + (l >> 2);
#pragma unroll
        for (int g = 0; g < 4; ++g)
#pragma unroll
            for (int nb = 0; nb < 2; ++nb) {
                int col = oc0 + wn * 64 + g * 16 + nb * 8 + (l & 3) * 2;
                float bv0 = g_bias[col], bv1 = g_bias[col + 1];
                float* v = acc[mb][g * 2 + nb];
                float* p0 = ob + (size_t)col * HWIMG;
                p0[r0]             = v[0] + bv0;
                p0[HWIMG + r0]     = v[1] + bv1;
                p0[r0 + 8]         = v[2] + bv0;
                p0[HWIMG + r0 + 8] = v[3] + bv1;
            }
    }
}

// ---------------------------------------------------------------------------
extern "C" void kernel_launch(void* const* d_in, const int* in_sizes, int n_in,
                              void* d_out, int out_size) {
    const float* X      = (const float*)d_in[0];
    const float* conv_w = (const float*)d_in[1];
    const float* conv_b = (const float*)d_in[2];
    const float* core1  = (const float*)d_in[3];
    const float* core2  = (const float*)d_in[4];
    const float* core3  = (const float*)d_in[5];
    float* out = (float*)d_out;

    stageA<<<1024, 256>>>(core1, core2);
    stageB<<<4096, 256>>>(core3);
    stageC<<<2304, 256>>>(conv_w);
    biasK<<<256, 256>>>(conv_b);
    splitW<<<2304, 256>>>();
    splitX<<<dim3(128, 8, 8), 256>>>(X);

    cudaFuncSetAttribute(conv_mma, cudaFuncAttributeMaxDynamicSharedMemorySize, SMEM_TOTAL);
    conv_mma<<<dim3(256, 2), 256, SMEM_TOTAL>>>(out);
}

// round 16
// speedup vs baseline: 4.6149x; 1.0734x over previous
#include <cuda_runtime.h>
#include <cuda_fp16.h>
#include <cstdint>

// ===========================================================================
// TTConv collapsed to a 256->256 3x3 conv (+ bias).
// Main GEMM on mma.sync fp16 single-term; M-tile 64 (one image row) x 128 oc,
// 1024 CTAs for fine wave quantization, 2 CTAs/SM.
// sm_103-baseline ISA only (no tcgen05 on this bench target).
// ===========================================================================

#define BATCH 8
#define CH    256
#define HH    64
#define WW    64
#define HWIMG (HH*WW)

// ---------------- scratch (__device__ globals; no allocation) --------------
__device__ float g_T[4 * 16 * 4 * 8 * 16 * 8];
__device__ float g_A[CH * 16 * CH];          // [ic][r][oc]
__device__ float g_W[2304 * CH];             // [ic*9+tap][oc]
__device__ float g_bias[CH];
__device__ alignas(256) __half g_W2[9 * CH * CH];        // [tap][oc][ic]
__device__ alignas(256) __half g_Xh[BATCH * HWIMG * CH]; // [b][h][w][ic]

// ---------------- PTX helpers (all sm_80+ baseline) -------------------------
__device__ __forceinline__ uint32_t smem_u32(const void* p) {
    uint32_t a;
    asm("{ .reg .u64 t; cvta.to.shared.u64 t, %1; cvt.u32.u64 %0, t; }" : "=r"(a) : "l"(p));
    return a;
}
__device__ __forceinline__ void cp16(uint32_t d, const void* s, int sz) {
    asm volatile("cp.async.cg.shared.global [%0], [%1], 16, %2;" :: "r"(d), "l"(s), "r"(sz) : "memory");
}
#define CP_COMMIT() asm volatile("cp.async.commit_group;" ::: "memory")
#define CP_WAIT(n)  asm volatile("cp.async.wait_group %0;" :: "n"(n) : "memory")

__device__ __forceinline__ void ldsm4(uint32_t* r, uint32_t addr) {
    asm volatile("ldmatrix.sync.aligned.m8n8.x4.shared.b16 {%0,%1,%2,%3}, [%4];"
        : "=r"(r[0]), "=r"(r[1]), "=r"(r[2]), "=r"(r[3]) : "r"(addr));
}
__device__ __forceinline__ void mma16816(float* c, const uint32_t* a, const uint32_t* b) {
    asm volatile(
        "mma.sync.aligned.m16n8k16.row.col.f32.f16.f16.f32 "
        "{%0,%1,%2,%3}, {%4,%5,%6,%7}, {%8,%9}, {%0,%1,%2,%3};"
        : "+f"(c[0]), "+f"(c[1]), "+f"(c[2]), "+f"(c[3])
        : "r"(a[0]), "r"(a[1]), "r"(a[2]), "r"(a[3]), "r"(b[0]), "r"(b[1]));
}

// ---------------- Stage A/B/C + bias (weight folding) ----------------------
__global__ void stageA(const float* __restrict__ core1, const float* __restrict__ core2) {
    int idx = blockIdx.x * blockDim.x + threadIdx.x;
    int j = idx & 7, v = (idx >> 3) & 15, c = (idx >> 7) & 7;
    int i = (idx >> 10) & 3, r = (idx >> 12) & 15, a = (idx >> 16) & 3;
    float s = 0.f;
#pragma unroll
    for (int u = 0; u < 16; u++)
        s += core1[(a * 16 + u) * 64 + r * 4 + i] * core2[(c * 16 + v) * 128 + u * 8 + j];
    g_T[idx] = s;
}
__global__ void stageB(const float* __restrict__ core3) {
    int idx = blockIdx.x * blockDim.x + threadIdx.x;
    int oc = idx & 255, r = (idx >> 8) & 15, ic = idx >> 12;
    int k = ic & 7, j = (ic >> 3) & 7, i = ic >> 6;
    int d = oc & 7, c = (oc >> 3) & 7, a = oc >> 6;
    float s = 0.f;
#pragma unroll
    for (int v = 0; v < 16; v++)
        s += g_T[((((a * 16 + r) * 4 + i) * 8 + c) * 16 + v) * 8 + j] * core3[d * 128 + v * 8 + k];
    g_A[idx] = s;
}
__global__ void stageC(const float* __restrict__ conv_w) {
    int idx = blockIdx.x * blockDim.x + threadIdx.x;
    int oc = idx & 255, kk = idx >> 8;
    int ic = kk / 9, tap = kk - ic * 9;
    float s = 0.f;
#pragma unroll
    for (int r = 0; r < 16; r++)
        s += g_A[(ic * 16 + r) * 256 + oc] * conv_w[r * 9 + tap];
    g_W[idx] = s;
}
__global__ void biasK(const float* __restrict__ conv_b) {
    __shared__ float red[256];
    const int oc = blockIdx.x, t = threadIdx.x;
    float s = 0.f;
#pragma unroll
    for (int r = 0; r < 16; r++)
        s += g_A[(t * 16 + r) * 256 + oc] * conv_b[r];
    red[t] = s;
    __syncthreads();
#pragma unroll
    for (int off = 128; off > 0; off >>= 1) {
        if (t < off) red[t] += red[t + off];
        __syncthreads();
    }
    if (t == 0) g_bias[oc] = red[0];
}

// ---------------- weight reorder to fp16: W2[tap][oc][ic] ------------------
__global__ void splitW() {
    int idx = blockIdx.x * 256 + threadIdx.x;   // < 9*256*256
    int ic = idx & 255, oc = (idx >> 8) & 255, tap = idx >> 16;
    g_W2[idx] = __float2half(g_W[(ic * 9 + tap) * 256 + oc]);
}

// ---------------- X transpose to fp16: X_t[b][h][w][ic] --------------------
__global__ void splitX(const float* __restrict__ X) {
    __shared__ float tile[32][33];
    const int b = blockIdx.z;
    const int hwt = blockIdx.x * 32, ict = blockIdx.y * 32;
    const int tx = threadIdx.x & 31, ty = threadIdx.x >> 5;   // ty 0..7
#pragma unroll
    for (int i = 0; i < 4; i++) {
        int ic = ict + ty + i * 8;
        tile[ty + i * 8][tx] = X[((b * CH + ic) * HWIMG) + hwt + tx];
    }
    __syncthreads();
#pragma unroll
    for (int i = 0; i < 4; i++) {
        int hw = hwt + ty + i * 8;
        int ic = ict + tx;
        long o = (long)(b * HWIMG + hw) * CH + ic;
        g_Xh[o] = __float2half(tile[tx][ty + i * 8]);
    }
}

// ---------------------------------------------------------------------------
// Main mma.sync kernel: CTA tile 64(m = one image row) x 128(oc).
// K = 9 taps x 8 ic-chunks of 32 = 72 chunks. 4-stage cp.async pipeline.
// 8 warps (2m x 4oc), warp tile 32x32. fp16 single-term, fp32 accumulate.
// Smem rows 32 fp16 padded to 80 B pitch -> ldmatrix conflict-free.
// ---------------------------------------------------------------------------
#define PITCH 80
#define OFF_A  0
#define OFF_B  (64 * PITCH)            // A: 64 rows
#define STG    (OFF_B + 128 * PITCH)   // 15360 per stage
#define NSTAGE 4
#define SMEM_TOTAL (STG * NSTAGE)      // 61440
#define NC 72

__global__ __launch_bounds__(256, 2) void conv_mma(float* __restrict__ out) {
    extern __shared__ char smem[];
    const uint32_t sb = smem_u32(smem);
    const int tid = threadIdx.x;
    const int l = tid & 31, wid = tid >> 5;
    const int wm = wid & 1, wn = wid >> 1;       // warp tile origin (wm*32 m, wn*32 oc)
    const int m0  = blockIdx.x * 64;             // one image row
    const int oc0 = blockIdx.y * 128;
    const int b   = m0 >> 12;
    const int lh  = (m0 >> 6) & 63;              // fixed h for this tile

    // loader indices: A: tid -> (w = tid>>2, 16B seg tid&3); B: (row tid>>1, half tid&1)
    const int aw = tid >> 2, aseg = tid & 3;
    const int brow = tid >> 1, bhalf = tid & 1;

    auto load = [&](int c, int s) {
        const int tap = c >> 3;                  // c = tap*8 + ic-chunk
        const int icc = (c & 7) * 32;
        const int dh = tap / 3 - 1, dw = tap % 3 - 1;
        const uint32_t base = sb + s * STG;
        // A: 64 rows x 64 B (one 16B seg per thread), halo zero-fill
        int hv = lh + dh, wv = aw + dw;
        bool ok = ((unsigned)hv < 64u) & ((unsigned)wv < 64u);
        int sz = ok ? 16 : 0;
        long pix = (long)(b << 12) + (ok ? hv * 64 + wv : 0);
        const __half* sa = g_Xh + pix * CH + icc + aseg * 8;
        cp16(base + OFF_A + aw * PITCH + aseg * 16, sa, sz);
        // B: 128 oc rows x 64 B (two 16B per thread)
        const __half* sbw = g_W2 + ((tap * 256 + oc0 + brow) * 256 + icc + bhalf * 16);
        uint32_t db = base + OFF_B + brow * PITCH + bhalf * 32;
        cp16(db,      sbw,     16);
        cp16(db + 16, sbw + 8, 16);
        CP_COMMIT();
    };

    float acc[2][4][4];
#pragma unroll
    for (int i = 0; i < 2; i++)
#pragma unroll
        for (int j = 0; j < 4; j++)
#pragma unroll
            for (int q = 0; q < 4; q++) acc[i][j][q] = 0.f;

    load(0, 0); load(1, 1); load(2, 2);

    // fragment addressing (ldmatrix lane rows)
    const uint32_t a_row = wm * 32 + (l & 15);
    const uint32_t a_seg = (uint32_t)(l >> 4) * 16;
    const uint32_t b_row = wn * 32 + ((l >> 4) << 3) + (l & 7);
    const uint32_t b_seg = (uint32_t)((l >> 3) & 1) * 16;

    for (int c = 0; c < NC; ++c) {
        CP_WAIT(2);
        __syncthreads();
        const uint32_t base = sb + (uint32_t)(c & 3) * STG;
#pragma unroll
        for (int k16 = 0; k16 < 2; ++k16) {
            uint32_t ah[2][4], bh[2][4];
#pragma unroll
            for (int mb = 0; mb < 2; ++mb) {
                uint32_t ad = base + OFF_A + (a_row + mb * 16) * PITCH + k16 * 32 + a_seg;
                ldsm4(ah[mb], ad);
            }
#pragma unroll
            for (int g = 0; g < 2; ++g) {
                uint32_t bd = base + OFF_B + (b_row + g * 16) * PITCH + k16 * 32 + b_seg;
                ldsm4(bh[g], bd);
            }
#pragma unroll
            for (int mb = 0; mb < 2; ++mb)
#pragma unroll
                for (int g = 0; g < 2; ++g)
#pragma unroll
                    for (int nb = 0; nb < 2; ++nb)
                        mma16816(acc[mb][g * 2 + nb], ah[mb], &bh[g][nb * 2]);
        }
        if (c + 3 < NC) load(c + 3, (c + 3) & 3);
        else CP_COMMIT();                       // keep group accounting stable
    }

    // ---- epilogue: scatter accumulators + bias into out[b][oc][hw]
    const int hwbase = m0 & 4095;
    float* ob = out + (size_t)b * CH * HWIMG + hwbase;
#pragma unroll
    for (int mb = 0; mb < 2; ++mb) {
        int r0 = wm * 32 + mb * 16 + (l >> 2);
#pragma unroll
        for (int g = 0; g < 2; ++g)
#pragma unroll
            for (int nb = 0; nb < 2; ++nb) {
                int col = oc0 + wn * 32 + g * 16 + nb * 8 + (l & 3) * 2;
                float bv0 = g_bias[col], bv1 = g_bias[col + 1];
                float* v = acc[mb][g * 2 + nb];
                float* p0 = ob + (size_t)col * HWIMG;
                p0[r0]             = v[0] + bv0;
                p0[HWIMG + r0]     = v[1] + bv1;
                p0[r0 + 8]         = v[2] + bv0;
                p0[HWIMG + r0 + 8] = v[3] + bv1;
            }
    }
}

// ---------------------------------------------------------------------------
extern "C" void kernel_launch(void* const* d_in, const int* in_sizes, int n_in,
                              void* d_out, int out_size) {
    const float* X      = (const float*)d_in[0];
    const float* conv_w = (const float*)d_in[1];
    const float* conv_b = (const float*)d_in[2];
    const float* core1  = (const float*)d_in[3];
    const float* core2  = (const float*)d_in[4];
    const float* core3  = (const float*)d_in[5];
    float* out = (float*)d_out;

    stageA<<<1024, 256>>>(core1, core2);
    stageB<<<4096, 256>>>(core3);
    stageC<<<2304, 256>>>(conv_w);
    biasK<<<256, 256>>>(conv_b);
    splitW<<<2304, 256>>>();
    splitX<<<dim3(128, 8, 8), 256>>>(X);

    cudaFuncSetAttribute(conv_mma, cudaFuncAttributeMaxDynamicSharedMemorySize, SMEM_TOTAL);
    conv_mma<<<dim3(512, 2), 256, SMEM_TOTAL>>>(out);
}